// round 9
// baseline (speedup 1.0000x reference)
#include <cuda_runtime.h>
#include <cuda_bf16.h>

// RippleLinear: out[b,o] = sum_i amp[i,o]*sin(x[b,i]*freq[i,o] + bias[1+i,o]) + bias[0,o]
// R4 (re-bench after infra failure): BB=14, ISPLIT=4 -> 588 CTAs at 4 CTAs/SM = ONE wave.
// i unrolled by 4 with LDS.128 x loads. Hybrid sin split f=46/56~0.821:
// poly (FMA pipe) only for (j==3 && b<10), MUFU.SIN otherwise -> both pipes ~balanced.

#define I_DIM 256
#define O_DIM 256
#define BB 14
#define ISPLIT 4
#define IC (I_DIM / ISPLIT)   // 64

// Degree-11 odd Taylor sin — err ~3e-8 for |t|<=1.5.
__device__ __forceinline__ float sin_poly(float t) {
    float t2 = t * t;
    float p = fmaf(t2, -2.50521084e-8f, 2.75573192e-6f);
    p = fmaf(p, t2, -1.98412698e-4f);
    p = fmaf(p, t2,  8.33333333e-3f);
    p = fmaf(p, t2, -1.66666667e-1f);
    p = fmaf(p, t2,  1.0f);
    return t * p;
}

// Seed out with bias[0, :] so the main kernel can pure-atomicAdd partials.
__global__ __launch_bounds__(256) void init_kernel(
    const float* __restrict__ bias, float* __restrict__ out, int n)
{
    int idx = blockIdx.x * 256 + threadIdx.x;
    if (idx < n) out[idx] = bias[idx & (O_DIM - 1)];
}

__global__ __launch_bounds__(O_DIM, 4) void ripple_kernel(
    const float* __restrict__ x,      // [B, I]
    const float* __restrict__ w,      // [I, O, 2]  (amp, freq)
    const float* __restrict__ bias,   // [I+1, O]
    float* __restrict__ out,          // [B, O]  (pre-seeded with bias0)
    int B)
{
    __shared__ float xs[BB][IC];      // 3.5 KB

    const int o  = threadIdx.x;
    const int b0 = blockIdx.x * BB;
    const int i0 = blockIdx.y * IC;

    // Stage x tile: BB x IC floats = 224 float4 (clamp rows for tail block).
    {
        for (int k = threadIdx.x; k < BB * IC / 4; k += O_DIM) {
            int row = k / (IC / 4);
            int col = (k % (IC / 4)) * 4;
            int rg  = min(b0 + row, B - 1);
            float4 v = *reinterpret_cast<const float4*>(x + (size_t)rg * I_DIM + i0 + col);
            *reinterpret_cast<float4*>(&xs[row][col]) = v;
        }
    }
    __syncthreads();

    float acc[BB];
    #pragma unroll
    for (int b = 0; b < BB; b++) acc[b] = 0.0f;

    const float2* w2p = reinterpret_cast<const float2*>(w);  // [I][O] (amp,freq)

    for (int ii = 0; ii < IC; ii += 4) {
        const int i = i0 + ii;
        float2 w20 = __ldg(&w2p[(i + 0) * O_DIM + o]);
        float2 w21 = __ldg(&w2p[(i + 1) * O_DIM + o]);
        float2 w22 = __ldg(&w2p[(i + 2) * O_DIM + o]);
        float2 w23 = __ldg(&w2p[(i + 3) * O_DIM + o]);
        float  bi0 = __ldg(&bias[(i + 1) * O_DIM + o]);
        float  bi1 = __ldg(&bias[(i + 2) * O_DIM + o]);
        float  bi2 = __ldg(&bias[(i + 3) * O_DIM + o]);
        float  bi3 = __ldg(&bias[(i + 4) * O_DIM + o]);

        #pragma unroll
        for (int b = 0; b < BB; b++) {
            float4 xv = *reinterpret_cast<const float4*>(&xs[b][ii]);  // LDS.128 broadcast
            float t0 = fmaf(xv.x, w20.y, bi0);
            float t1 = fmaf(xv.y, w21.y, bi1);
            float t2 = fmaf(xv.z, w22.y, bi2);
            float t3 = fmaf(xv.w, w23.y, bi3);
            acc[b] = fmaf(w20.x, __sinf(t0), acc[b]);
            acc[b] = fmaf(w21.x, __sinf(t1), acc[b]);
            acc[b] = fmaf(w22.x, __sinf(t2), acc[b]);
            // f = 46/56 ~ 0.821: FMA-pipe poly for 10 of 14 b's on lane j=3 only.
            if (b < 10)
                acc[b] = fmaf(w23.x, sin_poly(t3), acc[b]);
            else
                acc[b] = fmaf(w23.x, __sinf(t3), acc[b]);
        }
    }

    #pragma unroll
    for (int b = 0; b < BB; b++) {
        if (b0 + b < B)
            atomicAdd(out + (size_t)(b0 + b) * O_DIM + o, acc[b]);
    }
}

extern "C" void kernel_launch(void* const* d_in, const int* in_sizes, int n_in,
                              void* d_out, int out_size) {
    const float* x    = (const float*)d_in[0];
    const float* w    = (const float*)d_in[1];
    const float* bias = (const float*)d_in[2];
    float* out = (float*)d_out;

    int B = in_sizes[0] / I_DIM;                  // 2048
    int n = B * O_DIM;

    init_kernel<<<(n + 255) / 256, 256>>>(bias, out, n);

    dim3 grid((B + BB - 1) / BB, ISPLIT);         // (147, 4) = 588 CTAs -> one full wave @ occ 4
    ripple_kernel<<<grid, O_DIM>>>(x, w, bias, out, B);
}